// round 2
// baseline (speedup 1.0000x reference)
#include <cuda_runtime.h>
#include <math.h>

// Problem constants
constexpr int Hc   = 20;          // H
constexpr int H2c  = 40;          // 2H
constexpr int Tc   = 512;
constexpr int Dc   = 128;
constexpr int Nc   = 1024;
constexpr int KT   = 64;          // tail timesteps kept (alpha^62 < 1e-31, |alpha| < 0.317 guaranteed)
constexpr float PIf = 3.14159265358979323846f;

// Scratch (no allocations allowed)
__device__ float g_W[KT * Dc];    // per-timestep weight rows for t = T-KT .. T-1
__device__ float g_bias;

// ---------------------------------------------------------------------------
// Setup kernel: derive the rank-1 recurrence closed form.
//   recurrence(h) = (u . h) * z   (all linear; verified algebraically)
//   u_j = Im[ (w_j/sqrt(H)) * (1 - s1 * V_m * conj(v1_0)) ]   (FFT of a delta)
//   z   = D3 * R2 * IFFT * z0
//   y_n = q.x[n,T-1] + beta * sum_t alpha^{T-2-t} (p.x[n,t]) + beta*alpha^{T-1}*a0
// ---------------------------------------------------------------------------
__global__ void setup_kernel(const float* __restrict__ Cw,    // (40,128)
                             const float* __restrict__ Bw,    // (1,40)
                             const float* __restrict__ refl,  // (2,40)
                             const float* __restrict__ theta, // (3,20)
                             const float* __restrict__ mu0)   // (20,)
{
    __shared__ float  su[H2c];
    __shared__ float  sz[H2c];
    __shared__ float  scoef[KT];
    __shared__ float2 so[Hc];
    __shared__ float2 s_t2;

    const int tid = threadIdx.x;
    const float INV_SQRT_H = 1.0f / sqrtf((float)Hc);

    // ---- Stage A: u_j = component H of (R1 * FFT/sqrtH * D1) e_j ----
    if (tid < H2c) {
        const int j = tid;
        const int m = (j < Hc) ? j : j - Hc;
        const float th0 = theta[m];            // theta[0] row
        float2 w;                              // D1 applied to basis vector
        if (j < Hc) w = make_float2(cosf(th0), sinf(th0));
        else        w = make_float2(-sinf(th0), cosf(th0));   // i * e^{i th}

        float vss = 0.f;
        for (int k = 0; k < H2c; k++) { float r = refl[k]; vss += r * r; }
        const float sc1 = 2.0f / vss;

        // V_m = sum_k v_k * exp(-2*pi*i*m*k/H)
        float2 V = make_float2(0.f, 0.f);
        for (int k = 0; k < Hc; k++) {
            const int mm = (m * k) % Hc;
            const float ang = -2.0f * PIf * (float)mm / (float)Hc;
            float sk, ck; sincosf(ang, &sk, &ck);
            const float vr = refl[k], vi = refl[Hc + k];
            V.x += vr * ck - vi * sk;
            V.y += vr * sk + vi * ck;
        }
        const float2 v0c = make_float2(refl[0], -refl[Hc]);   // conj(v1_0)
        float2 g;
        g.x = 1.0f - sc1 * (V.x * v0c.x - V.y * v0c.y);
        g.y =        -sc1 * (V.x * v0c.y + V.y * v0c.x);
        su[j] = (w.x * g.y + w.y * g.x) * INV_SQRT_H;         // Im(w*g)/sqrtH
    }

    // ---- Stage B1: o = IFFT(z0)/sqrtH ;  z0_m = (c-s) + i(c+s) from theta[1] ----
    if (tid < Hc) {
        const int k = tid;
        float2 acc = make_float2(0.f, 0.f);
        for (int m = 0; m < Hc; m++) {
            const float th1 = theta[Hc + m];
            float s1v, c1; sincosf(th1, &s1v, &c1);
            const float2 z0 = make_float2(c1 - s1v, c1 + s1v);
            const int mm = (m * k) % Hc;
            const float ang = 2.0f * PIf * (float)mm / (float)Hc;
            float sk, ck; sincosf(ang, &sk, &ck);
            acc.x += z0.x * ck - z0.y * sk;
            acc.y += z0.x * sk + z0.y * ck;
        }
        const float scale = 1.0f / ((float)Hc * sqrtf((float)Hc));
        so[k] = make_float2(acc.x * scale, acc.y * scale);
    }
    __syncthreads();

    // ---- Stage B2: reflection-2 bilinear dot t2 = s2 * (v2^T o) ----
    if (tid == 0) {
        float vss2 = 0.f;
        for (int k = 0; k < H2c; k++) { float r = refl[H2c + k]; vss2 += r * r; }
        float2 t = make_float2(0.f, 0.f);
        for (int k = 0; k < Hc; k++) {
            const float vr = refl[H2c + k], vi = refl[H2c + Hc + k];
            t.x += vr * so[k].x - vi * so[k].y;
            t.y += vr * so[k].y + vi * so[k].x;
        }
        const float s2 = 2.0f / vss2;
        s_t2 = make_float2(t.x * s2, t.y * s2);
    }
    __syncthreads();

    // ---- Stage B3: apply reflection + D3(theta[2]) -> z ----
    if (tid < Hc) {
        const int k = tid;
        const float vr = refl[H2c + k], vi = refl[H2c + Hc + k];
        float2 o = so[k];
        // o -= t2 * conj(v2_k)
        o.x -= s_t2.x * vr + s_t2.y * vi;
        o.y -= s_t2.y * vr - s_t2.x * vi;
        const float th2 = theta[2 * Hc + k];
        float s, c; sincosf(th2, &s, &c);
        sz[k]      = o.x * c - o.y * s;
        sz[Hc + k] = o.x * s + o.y * c;
    }
    __syncthreads();

    // ---- Stage C: scalars alpha, beta, a0, coefficient ladder, bias ----
    if (tid == 0) {
        float alpha = 0.f, beta = 0.f, a0 = 0.f;
        for (int j = 0; j < H2c; j++) { alpha += su[j] * sz[j]; beta += sz[j] * Bw[j]; }
        for (int j = 0; j < Hc;  j++) a0 += mu0[j] * (su[j] - su[Hc + j]);

        // coef[k] = beta * alpha^{KT-2-k} for timestep t = T-KT+k (t <= T-2)
        float c = beta;
        for (int k = KT - 2; k >= 0; k--) { scoef[k] = c; c *= alpha; }
        scoef[KT - 1] = 0.f;   // t = T-1 handled by q

        // bias = beta * a0 * alpha^{T-1}  (|alpha|<0.317 -> underflows to exact 0)
        float bp = beta * a0;
        for (int e = 0; e < Tc - 1 && bp != 0.f; e++) bp *= alpha;
        g_bias = bp;
    }
    __syncthreads();

    // ---- Stage D/E: p = Cw^T u, q = Cw^T b, materialize W ----
    if (tid < Dc) {
        const int d = tid;
        float p = 0.f, q = 0.f;
        for (int j = 0; j < H2c; j++) {
            const float cw = Cw[j * Dc + d];
            p += su[j] * cw;
            q += Bw[j] * cw;
        }
        for (int k = 0; k < KT - 1; k++) g_W[k * Dc + d] = scoef[k] * p;
        g_W[(KT - 1) * Dc + d] = q;
    }
}

// ---------------------------------------------------------------------------
// Main kernel: y[n] = bias + sum over last KT timesteps of x[n,t,:] . W[t,:]
// One block per row; W staged in shared memory; float4 coalesced streaming.
// ---------------------------------------------------------------------------
__global__ __launch_bounds__(256, 4)
void urnn_reduce_kernel(const float* __restrict__ x, float* __restrict__ out)
{
    constexpr int NV4 = KT * Dc / 4;          // 2048 float4
    __shared__ float4 sW[NV4];
    const int tid = threadIdx.x;

    const float4* Wg = reinterpret_cast<const float4*>(g_W);
    #pragma unroll
    for (int i = tid; i < NV4; i += 256) sW[i] = Wg[i];
    __syncthreads();

    const int n = blockIdx.x;
    const float4* xp = reinterpret_cast<const float4*>(
        x + (size_t)n * (Tc * Dc) + (size_t)(Tc - KT) * Dc);

    float acc = 0.f;
    #pragma unroll
    for (int r = 0; r < NV4 / 256; r++) {
        const int idx = tid + r * 256;
        const float4 a = xp[idx];
        const float4 w = sW[idx];
        acc += a.x * w.x + a.y * w.y + a.z * w.z + a.w * w.w;
    }

    // block reduction: warp shuffle then cross-warp
    #pragma unroll
    for (int off = 16; off; off >>= 1) acc += __shfl_down_sync(0xffffffffu, acc, off);
    __shared__ float warpsum[8];
    if ((tid & 31) == 0) warpsum[tid >> 5] = acc;
    __syncthreads();
    if (tid < 8) {
        float v = warpsum[tid];
        #pragma unroll
        for (int off = 4; off; off >>= 1) v += __shfl_down_sync(0xffu, v, off);
        if (tid == 0) out[n] = v + g_bias;
    }
}

extern "C" void kernel_launch(void* const* d_in, const int* in_sizes, int n_in,
                              void* d_out, int out_size)
{
    const float* inputs = (const float*)d_in[0];   // (1024, 512, 128)
    const float* C_w    = (const float*)d_in[1];   // (40, 128)
    const float* B_w    = (const float*)d_in[2];   // (1, 40)
    const float* refl   = (const float*)d_in[3];   // (2, 40)
    const float* theta  = (const float*)d_in[4];   // (3, 20)
    const float* mu0    = (const float*)d_in[5];   // (20,)
    float* out = (float*)d_out;                    // (1024,)

    setup_kernel<<<1, 128>>>(C_w, B_w, refl, theta, mu0);
    urnn_reduce_kernel<<<Nc, 256>>>(inputs, out);
}

// round 3
// speedup vs baseline: 1.6911x; 1.6911x over previous
#include <cuda_runtime.h>
#include <math.h>

// Problem constants
constexpr int Hc   = 20;          // H
constexpr int H2c  = 40;          // 2H
constexpr int Tc   = 512;
constexpr int Dc   = 128;
constexpr int Nc   = 1024;
constexpr int KT   = 64;          // tail timesteps kept (|alpha| < 0.317 guaranteed -> alpha^62 < 1e-31)
constexpr float PIf = 3.14159265358979323846f;

// ---------------------------------------------------------------------------
// Fused kernel. Math identical to the verified 2-kernel version:
//   recurrence(h) = (u . h) * z  (rank-1), so
//   y_n = q.x[n,T-1] + beta * sum_k alpha^{62-k} (p.x[n,448+k]) + beta*a0*alpha^{T-1}
// Each block redundantly computes {p,q,scoef,bias} (cheap: twiddle table kills
// the sincosf cost) while its 32KB x-tail streams in via cp.async.
// ---------------------------------------------------------------------------
__global__ __launch_bounds__(256)
void urnn_fused(const float* __restrict__ x,     // (1024,512,128)
                const float* __restrict__ Cw,    // (40,128)
                const float* __restrict__ Bw,    // (1,40)
                const float* __restrict__ refl,  // (2,40)
                const float* __restrict__ theta, // (3,20)
                const float* __restrict__ mu0,   // (20,)
                float* __restrict__ out)         // (1024,)
{
    __shared__ float4 sX[KT * Dc / 4];           // 32 KB x tail
    __shared__ float tw_c[Hc], tw_s[Hc];         // exp(+2*pi*i*k/H) table
    __shared__ float e0c[Hc], e0s[Hc];           // e^{i theta0}
    __shared__ float z0r[Hc], z0i[Hc];           // (c-s, c+s) from theta1
    __shared__ float e2c[Hc], e2s[Hc];           // e^{i theta2}
    __shared__ float r1[H2c], r2[H2c], sBw[H2c];
    __shared__ float su[H2c], szv[H2c];
    __shared__ float so_r[Hc], so_i[Hc];
    __shared__ float sp[Dc], sq[Dc], scoef[KT];
    __shared__ float vss1s, vss2s, t2x, t2y, sbias;
    __shared__ float wsum[8];

    const int tid = threadIdx.x;
    const int n   = blockIdx.x;

    // ---- Issue the x-tail loads FIRST (async, L2->smem, no regs held) ----
    const float4* xp = reinterpret_cast<const float4*>(
        x + (size_t)n * (Tc * Dc) + (size_t)(Tc - KT) * Dc);
    #pragma unroll
    for (int r = 0; r < 8; r++) {
        const int idx = tid + r * 256;
        unsigned sa = (unsigned)__cvta_generic_to_shared(&sX[idx]);
        asm volatile("cp.async.cg.shared.global [%0], [%1], 16;\n"
                     :: "r"(sa), "l"(xp + idx));
    }
    asm volatile("cp.async.commit_group;\n");

    // ---- Pre-stage: trig tables + small operand staging ----
    if (tid < Hc) {
        float s, c;
        sincosf(2.0f * PIf * (float)tid / (float)Hc, &s, &c);
        tw_c[tid] = c; tw_s[tid] = s;
        sincosf(theta[tid], &s, &c);          e0c[tid] = c; e0s[tid] = s;
        sincosf(theta[Hc + tid], &s, &c);     z0r[tid] = c - s; z0i[tid] = c + s;
        sincosf(theta[2 * Hc + tid], &s, &c); e2c[tid] = c; e2s[tid] = s;
    }
    if (tid >= 32 && tid < 32 + H2c) {
        const int j = tid - 32;
        r1[j] = refl[j]; r2[j] = refl[H2c + j]; sBw[j] = Bw[j];
    }
    if (tid == 96)  { float v = 0.f; for (int k = 0; k < H2c; k++) { float r = refl[k];       v += r * r; } vss1s = v; }
    if (tid == 128) { float v = 0.f; for (int k = 0; k < H2c; k++) { float r = refl[H2c + k]; v += r * r; } vss2s = v; }
    __syncthreads();

    // ---- Stage A (warps 0-1): u_j = Im[(w_j/sqrtH)(1 - s1 V_m conj(v1_0))] ----
    if (tid < H2c) {
        const int j = tid;
        const int m = (j < Hc) ? j : j - Hc;
        float2 w;
        if (j < Hc) w = make_float2(e0c[m], e0s[m]);
        else        w = make_float2(-e0s[m], e0c[m]);     // i * e^{i th}
        const float sc1 = 2.0f / vss1s;
        float Vx = 0.f, Vy = 0.f;
        #pragma unroll 4
        for (int k = 0; k < Hc; k++) {
            const int mm = (m * k) % Hc;
            const float ck = tw_c[mm], sk = -tw_s[mm];    // exp(-2*pi*i*mm/H)
            const float vr = r1[k], vi = r1[Hc + k];
            Vx += vr * ck - vi * sk;
            Vy += vr * sk + vi * ck;
        }
        const float v0x = r1[0], v0y = -r1[Hc];           // conj(v1_0)
        const float gx = 1.0f - sc1 * (Vx * v0x - Vy * v0y);
        const float gy =        -sc1 * (Vx * v0y + Vy * v0x);
        su[j] = (w.x * gy + w.y * gx) * (1.0f / sqrtf((float)Hc));
    }
    // ---- Stage B1 (warp 2, concurrent): o = IFFT(z0)/sqrtH ----
    if (tid >= 64 && tid < 64 + Hc) {
        const int k = tid - 64;
        float ar = 0.f, ai = 0.f;
        #pragma unroll 4
        for (int m = 0; m < Hc; m++) {
            const int mm = (m * k) % Hc;
            const float ck = tw_c[mm], sk = tw_s[mm];     // exp(+2*pi*i*mm/H)
            ar += z0r[m] * ck - z0i[m] * sk;
            ai += z0r[m] * sk + z0i[m] * ck;
        }
        const float scale = 1.0f / ((float)Hc * sqrtf((float)Hc));
        so_r[k] = ar * scale; so_i[k] = ai * scale;
    }
    __syncthreads();

    // ---- Stage B2: t2 = s2 * (v2^T o);  Stage D (warps 4-7): p = Cw^T u, q = Cw^T b ----
    if (tid == 0) {
        float tx = 0.f, ty = 0.f;
        for (int k = 0; k < Hc; k++) {
            const float vr = r2[k], vi = r2[Hc + k];
            tx += vr * so_r[k] - vi * so_i[k];
            ty += vr * so_i[k] + vi * so_r[k];
        }
        const float s2 = 2.0f / vss2s;
        t2x = tx * s2; t2y = ty * s2;
    }
    if (tid >= 128) {
        const int d = tid - 128;
        float p = 0.f, q = 0.f;
        #pragma unroll 8
        for (int j = 0; j < H2c; j++) {
            const float cw = Cw[j * Dc + d];
            p += su[j] * cw;
            q += sBw[j] * cw;
        }
        sp[d] = p; sq[d] = q;
    }
    __syncthreads();

    // ---- Stage B3: apply reflection-2 + D3(theta2) -> z ----
    if (tid < Hc) {
        const int k = tid;
        const float vr = r2[k], vi = r2[Hc + k];
        const float ox = so_r[k] - (t2x * vr + t2y * vi);
        const float oy = so_i[k] - (t2y * vr - t2x * vi);
        const float c = e2c[k], s = e2s[k];
        szv[k]      = ox * c - oy * s;
        szv[Hc + k] = ox * s + oy * c;
    }
    __syncthreads();

    // ---- Stage C: alpha, beta, a0, coefficient ladder, bias ----
    if (tid == 0) {
        float alpha = 0.f, beta = 0.f, a0 = 0.f;
        for (int j = 0; j < H2c; j++) { alpha += su[j] * szv[j]; beta += szv[j] * sBw[j]; }
        for (int j = 0; j < Hc;  j++) a0 += mu0[j] * (su[j] - su[Hc + j]);
        float c = beta;
        for (int k = KT - 2; k >= 0; k--) { scoef[k] = c; c *= alpha; }
        scoef[KT - 1] = 1.0f;                               // row 63 uses q directly
        float bp = beta * a0;
        for (int e = 0; e < Tc - 1 && bp != 0.f; e++) bp *= alpha;
        sbias = bp;
    }

    // ---- Wait for x tail, then dot ----
    asm volatile("cp.async.wait_group 0;\n" ::: "memory");
    __syncthreads();

    const int lane = tid & 31, warp = tid >> 5;
    const float4 pv = reinterpret_cast<const float4*>(sp)[lane];
    const float4 qv = reinterpret_cast<const float4*>(sq)[lane];
    float acc = 0.f;
    #pragma unroll
    for (int r = 0; r < 8; r++) {
        const int k = warp + r * 8;                        // uniform per warp
        const float4 xv = sX[tid + r * 256];
        const float4 wv = (k == KT - 1) ? qv : pv;
        const float d = xv.x * wv.x + xv.y * wv.y + xv.z * wv.z + xv.w * wv.w;
        acc += scoef[k] * d;
    }

    #pragma unroll
    for (int off = 16; off; off >>= 1) acc += __shfl_down_sync(0xffffffffu, acc, off);
    if (lane == 0) wsum[warp] = acc;
    __syncthreads();
    if (tid < 8) {
        float v = wsum[tid];
        #pragma unroll
        for (int off = 4; off; off >>= 1) v += __shfl_down_sync(0xffu, v, off);
        if (tid == 0) out[n] = v + sbias;
    }
}

extern "C" void kernel_launch(void* const* d_in, const int* in_sizes, int n_in,
                              void* d_out, int out_size)
{
    const float* inputs = (const float*)d_in[0];   // (1024, 512, 128)
    const float* C_w    = (const float*)d_in[1];   // (40, 128)
    const float* B_w    = (const float*)d_in[2];   // (1, 40)
    const float* refl   = (const float*)d_in[3];   // (2, 40)
    const float* theta  = (const float*)d_in[4];   // (3, 20)
    const float* mu0    = (const float*)d_in[5];   // (20,)
    float* out = (float*)d_out;                    // (1024,)

    urnn_fused<<<Nc, 256>>>(inputs, C_w, B_w, refl, theta, mu0, out);
}

// round 4
// speedup vs baseline: 1.9873x; 1.1751x over previous
#include <cuda_runtime.h>
#include <math.h>

// Problem constants
constexpr int Hc   = 20;          // H
constexpr int H2c  = 40;          // 2H
constexpr int Tc   = 512;
constexpr int Dc   = 128;
constexpr int Nc   = 1024;
constexpr int KT   = 64;          // tail timesteps kept (|alpha| < 0.317 -> alpha^62 < 1e-31)
constexpr float PIf = 3.14159265358979323846f;

// Tiny derived operands (1 KB total) — L2-broadcast to all reduce blocks.
__device__ float g_p[Dc];
__device__ float g_q[Dc];
__device__ float g_coef[KT];
__device__ float g_bias;

// ---------------------------------------------------------------------------
// Setup kernel (1 block): derive the rank-1 closed form.
//   recurrence(h) = (u . h) * z
//   y_n = q.x[n,T-1] + sum_k coef[k] (p.x[n,448+k]) + bias,  coef[k]=beta*alpha^{62-k}
// Twiddle-table version (no per-element sincosf in inner loops).
// ---------------------------------------------------------------------------
__global__ void setup_kernel(const float* __restrict__ Cw,    // (40,128)
                             const float* __restrict__ Bw,    // (1,40)
                             const float* __restrict__ refl,  // (2,40)
                             const float* __restrict__ theta, // (3,20)
                             const float* __restrict__ mu0)   // (20,)
{
    __shared__ float tw_c[Hc], tw_s[Hc];
    __shared__ float e0c[Hc], e0s[Hc];
    __shared__ float z0r[Hc], z0i[Hc];
    __shared__ float e2c[Hc], e2s[Hc];
    __shared__ float r1[H2c], r2[H2c], sBw[H2c];
    __shared__ float su[H2c], szv[H2c];
    __shared__ float so_r[Hc], so_i[Hc];
    __shared__ float vss1s, vss2s, t2x, t2y;

    const int tid = threadIdx.x;

    if (tid < Hc) {
        float s, c;
        sincosf(2.0f * PIf * (float)tid / (float)Hc, &s, &c);
        tw_c[tid] = c; tw_s[tid] = s;
        sincosf(theta[tid], &s, &c);          e0c[tid] = c; e0s[tid] = s;
        sincosf(theta[Hc + tid], &s, &c);     z0r[tid] = c - s; z0i[tid] = c + s;
        sincosf(theta[2 * Hc + tid], &s, &c); e2c[tid] = c; e2s[tid] = s;
    }
    if (tid >= 32 && tid < 32 + H2c) {
        const int j = tid - 32;
        r1[j] = refl[j]; r2[j] = refl[H2c + j]; sBw[j] = Bw[j];
    }
    if (tid == 96)  { float v = 0.f; for (int k = 0; k < H2c; k++) { float r = refl[k];       v += r * r; } vss1s = v; }
    if (tid == 128) { float v = 0.f; for (int k = 0; k < H2c; k++) { float r = refl[H2c + k]; v += r * r; } vss2s = v; }
    __syncthreads();

    // Stage A: u_j = Im[(w_j/sqrtH)(1 - s1 V_m conj(v1_0))]
    if (tid < H2c) {
        const int j = tid;
        const int m = (j < Hc) ? j : j - Hc;
        float2 w;
        if (j < Hc) w = make_float2(e0c[m], e0s[m]);
        else        w = make_float2(-e0s[m], e0c[m]);     // i * e^{i th}
        const float sc1 = 2.0f / vss1s;
        float Vx = 0.f, Vy = 0.f;
        #pragma unroll 4
        for (int k = 0; k < Hc; k++) {
            const int mm = (m * k) % Hc;
            const float ck = tw_c[mm], sk = -tw_s[mm];    // exp(-2*pi*i*mm/H)
            const float vr = r1[k], vi = r1[Hc + k];
            Vx += vr * ck - vi * sk;
            Vy += vr * sk + vi * ck;
        }
        const float v0x = r1[0], v0y = -r1[Hc];           // conj(v1_0)
        const float gx = 1.0f - sc1 * (Vx * v0x - Vy * v0y);
        const float gy =        -sc1 * (Vx * v0y + Vy * v0x);
        su[j] = (w.x * gy + w.y * gx) * (1.0f / sqrtf((float)Hc));
    }
    // Stage B1 (concurrent warp): o = IFFT(z0)/sqrtH
    if (tid >= 64 && tid < 64 + Hc) {
        const int k = tid - 64;
        float ar = 0.f, ai = 0.f;
        #pragma unroll 4
        for (int m = 0; m < Hc; m++) {
            const int mm = (m * k) % Hc;
            const float ck = tw_c[mm], sk = tw_s[mm];
            ar += z0r[m] * ck - z0i[m] * sk;
            ai += z0r[m] * sk + z0i[m] * ck;
        }
        const float scale = 1.0f / ((float)Hc * sqrtf((float)Hc));
        so_r[k] = ar * scale; so_i[k] = ai * scale;
    }
    __syncthreads();

    // Stage B2: t2 = s2 * (v2^T o); Stage D (warps 4-7): p = Cw^T u, q = Cw^T b
    if (tid == 0) {
        float tx = 0.f, ty = 0.f;
        for (int k = 0; k < Hc; k++) {
            const float vr = r2[k], vi = r2[Hc + k];
            tx += vr * so_r[k] - vi * so_i[k];
            ty += vr * so_i[k] + vi * so_r[k];
        }
        const float s2 = 2.0f / vss2s;
        t2x = tx * s2; t2y = ty * s2;
    }
    if (tid >= 128) {
        const int d = tid - 128;
        float p = 0.f, q = 0.f;
        #pragma unroll 8
        for (int j = 0; j < H2c; j++) {
            const float cw = Cw[j * Dc + d];
            p += su[j] * cw;
            q += sBw[j] * cw;
        }
        g_p[d] = p; g_q[d] = q;
    }
    __syncthreads();

    // Stage B3: apply reflection-2 + D3(theta2) -> z
    if (tid < Hc) {
        const int k = tid;
        const float vr = r2[k], vi = r2[Hc + k];
        const float ox = so_r[k] - (t2x * vr + t2y * vi);
        const float oy = so_i[k] - (t2y * vr - t2x * vi);
        const float c = e2c[k], s = e2s[k];
        szv[k]      = ox * c - oy * s;
        szv[Hc + k] = ox * s + oy * c;
    }
    __syncthreads();

    // Stage C: alpha, beta, a0, ladder, bias
    if (tid == 0) {
        float alpha = 0.f, beta = 0.f, a0 = 0.f;
        for (int j = 0; j < H2c; j++) { alpha += su[j] * szv[j]; beta += szv[j] * sBw[j]; }
        for (int j = 0; j < Hc;  j++) a0 += mu0[j] * (su[j] - su[Hc + j]);
        float c = beta;
        for (int k = KT - 2; k >= 0; k--) { g_coef[k] = c; c *= alpha; }
        g_coef[KT - 1] = 1.0f;                 // slot for q (selected in reduce)
        float bp = beta * a0;
        for (int e = 0; e < Tc - 1 && bp != 0.f; e++) bp *= alpha;
        g_bias = bp;
    }
}

// ---------------------------------------------------------------------------
// Reduce kernel: y[n] = bias + sum_k coef[k]*(w_k . x[n,448+k,:])
// No smem staging, no barrier before the loads: weights are 1KB of
// L2-broadcast register state; 8 independent float4 LDGs in flight per thread.
// ---------------------------------------------------------------------------
__global__ __launch_bounds__(256)
void urnn_reduce(const float* __restrict__ x, float* __restrict__ out)
{
    const int tid  = threadIdx.x;
    const int lane = tid & 31;
    const int warp = tid >> 5;
    const int n    = blockIdx.x;

    const float4* xp = reinterpret_cast<const float4*>(
        x + (size_t)n * (Tc * Dc) + (size_t)(Tc - KT) * Dc);

    // Weight state (L1/L2 hits after first wave)
    const float4 pv = __ldg(&reinterpret_cast<const float4*>(g_p)[lane]);
    const float4 qv = __ldg(&reinterpret_cast<const float4*>(g_q)[lane]);
    float cf[8];
    #pragma unroll
    for (int r = 0; r < 8; r++) cf[r] = __ldg(&g_coef[warp + r * 8]);   // warp-uniform

    // Stream x: 8 independent float4 loads
    float4 xv[8];
    #pragma unroll
    for (int r = 0; r < 8; r++) xv[r] = xp[tid + r * 256];

    float acc = 0.f;
    #pragma unroll
    for (int r = 0; r < 8; r++) {
        const int k = warp + r * 8;
        const float4 wv = (k == KT - 1) ? qv : pv;
        const float d = xv[r].x * wv.x + xv[r].y * wv.y + xv[r].z * wv.z + xv[r].w * wv.w;
        acc += cf[r] * d;
    }

    #pragma unroll
    for (int off = 16; off; off >>= 1) acc += __shfl_down_sync(0xffffffffu, acc, off);
    __shared__ float wsum[8];
    if (lane == 0) wsum[warp] = acc;
    __syncthreads();
    if (tid < 8) {
        float v = wsum[tid];
        #pragma unroll
        for (int off = 4; off; off >>= 1) v += __shfl_down_sync(0xffu, v, off);
        if (tid == 0) out[n] = v + g_bias;
    }
}

extern "C" void kernel_launch(void* const* d_in, const int* in_sizes, int n_in,
                              void* d_out, int out_size)
{
    const float* inputs = (const float*)d_in[0];   // (1024, 512, 128)
    const float* C_w    = (const float*)d_in[1];   // (40, 128)
    const float* B_w    = (const float*)d_in[2];   // (1, 40)
    const float* refl   = (const float*)d_in[3];   // (2, 40)
    const float* theta  = (const float*)d_in[4];   // (3, 20)
    const float* mu0    = (const float*)d_in[5];   // (20,)
    float* out = (float*)d_out;                    // (1024,)

    setup_kernel<<<1, 256>>>(C_w, B_w, refl, theta, mu0);
    urnn_reduce<<<Nc, 256>>>(inputs, out);
}

// round 5
// speedup vs baseline: 2.1048x; 1.0591x over previous
#include <cuda_runtime.h>
#include <math.h>

// Problem constants
constexpr int Hc   = 20;          // H
constexpr int H2c  = 40;          // 2H
constexpr int Tc   = 512;
constexpr int Dc   = 128;
constexpr int Nc   = 1024;
// Tail timesteps kept. |alpha| <= |u||z| < 0.317 rigorously (u = row of an
// orthogonal matrix, |z| = sqrt(2H)/H), so truncation error ~ alpha^{KT-1}
// ≈ 3e-16 at KT=32 — far below fp32 rounding.
constexpr int KT   = 32;
constexpr float PIf = 3.14159265358979323846f;

// Tiny derived operands — L2-broadcast to all reduce blocks.
__device__ float g_p[Dc];
__device__ float g_q[Dc];
__device__ float g_coef[KT];
__device__ float g_bias;

// ---------------------------------------------------------------------------
// Setup kernel (1 block): derive the rank-1 closed form.
//   recurrence(h) = (u . h) * z
//   y_n = q.x[n,T-1] + sum_k coef[k] (p.x[n,T-KT+k]) + bias,
//   coef[k] = beta * alpha^{KT-2-k}
// ---------------------------------------------------------------------------
__global__ void setup_kernel(const float* __restrict__ Cw,    // (40,128)
                             const float* __restrict__ Bw,    // (1,40)
                             const float* __restrict__ refl,  // (2,40)
                             const float* __restrict__ theta, // (3,20)
                             const float* __restrict__ mu0)   // (20,)
{
    __shared__ float tw_c[Hc], tw_s[Hc];
    __shared__ float e0c[Hc], e0s[Hc];
    __shared__ float z0r[Hc], z0i[Hc];
    __shared__ float e2c[Hc], e2s[Hc];
    __shared__ float r1[H2c], r2[H2c], sBw[H2c];
    __shared__ float su[H2c], szv[H2c];
    __shared__ float so_r[Hc], so_i[Hc];
    __shared__ float vss1s, vss2s, t2x, t2y;

    const int tid = threadIdx.x;

    if (tid < Hc) {
        float s, c;
        sincosf(2.0f * PIf * (float)tid / (float)Hc, &s, &c);
        tw_c[tid] = c; tw_s[tid] = s;
        sincosf(theta[tid], &s, &c);          e0c[tid] = c; e0s[tid] = s;
        sincosf(theta[Hc + tid], &s, &c);     z0r[tid] = c - s; z0i[tid] = c + s;
        sincosf(theta[2 * Hc + tid], &s, &c); e2c[tid] = c; e2s[tid] = s;
    }
    if (tid >= 32 && tid < 32 + H2c) {
        const int j = tid - 32;
        r1[j] = refl[j]; r2[j] = refl[H2c + j]; sBw[j] = Bw[j];
    }
    if (tid == 96)  { float v = 0.f; for (int k = 0; k < H2c; k++) { float r = refl[k];       v += r * r; } vss1s = v; }
    if (tid == 128) { float v = 0.f; for (int k = 0; k < H2c; k++) { float r = refl[H2c + k]; v += r * r; } vss2s = v; }
    __syncthreads();

    // Stage A: u_j = Im[(w_j/sqrtH)(1 - s1 V_m conj(v1_0))]
    if (tid < H2c) {
        const int j = tid;
        const int m = (j < Hc) ? j : j - Hc;
        float2 w;
        if (j < Hc) w = make_float2(e0c[m], e0s[m]);
        else        w = make_float2(-e0s[m], e0c[m]);     // i * e^{i th}
        const float sc1 = 2.0f / vss1s;
        float Vx = 0.f, Vy = 0.f;
        #pragma unroll 4
        for (int k = 0; k < Hc; k++) {
            const int mm = (m * k) % Hc;
            const float ck = tw_c[mm], sk = -tw_s[mm];    // exp(-2*pi*i*mm/H)
            const float vr = r1[k], vi = r1[Hc + k];
            Vx += vr * ck - vi * sk;
            Vy += vr * sk + vi * ck;
        }
        const float v0x = r1[0], v0y = -r1[Hc];           // conj(v1_0)
        const float gx = 1.0f - sc1 * (Vx * v0x - Vy * v0y);
        const float gy =        -sc1 * (Vx * v0y + Vy * v0x);
        su[j] = (w.x * gy + w.y * gx) * (1.0f / sqrtf((float)Hc));
    }
    // Stage B1 (concurrent warp): o = IFFT(z0)/sqrtH
    if (tid >= 64 && tid < 64 + Hc) {
        const int k = tid - 64;
        float ar = 0.f, ai = 0.f;
        #pragma unroll 4
        for (int m = 0; m < Hc; m++) {
            const int mm = (m * k) % Hc;
            const float ck = tw_c[mm], sk = tw_s[mm];
            ar += z0r[m] * ck - z0i[m] * sk;
            ai += z0r[m] * sk + z0i[m] * ck;
        }
        const float scale = 1.0f / ((float)Hc * sqrtf((float)Hc));
        so_r[k] = ar * scale; so_i[k] = ai * scale;
    }
    __syncthreads();

    // Stage B2: t2 = s2 * (v2^T o); Stage D (warps 4-7): p = Cw^T u, q = Cw^T b
    if (tid == 0) {
        float tx = 0.f, ty = 0.f;
        for (int k = 0; k < Hc; k++) {
            const float vr = r2[k], vi = r2[Hc + k];
            tx += vr * so_r[k] - vi * so_i[k];
            ty += vr * so_i[k] + vi * so_r[k];
        }
        const float s2 = 2.0f / vss2s;
        t2x = tx * s2; t2y = ty * s2;
    }
    if (tid >= 128) {
        const int d = tid - 128;
        float p = 0.f, q = 0.f;
        #pragma unroll 8
        for (int j = 0; j < H2c; j++) {
            const float cw = Cw[j * Dc + d];
            p += su[j] * cw;
            q += sBw[j] * cw;
        }
        g_p[d] = p; g_q[d] = q;
    }
    __syncthreads();

    // Stage B3: apply reflection-2 + D3(theta2) -> z
    if (tid < Hc) {
        const int k = tid;
        const float vr = r2[k], vi = r2[Hc + k];
        const float ox = so_r[k] - (t2x * vr + t2y * vi);
        const float oy = so_i[k] - (t2y * vr - t2x * vi);
        const float c = e2c[k], s = e2s[k];
        szv[k]      = ox * c - oy * s;
        szv[Hc + k] = ox * s + oy * c;
    }
    __syncthreads();

    // Stage C: alpha, beta, a0, ladder, bias
    if (tid == 0) {
        float alpha = 0.f, beta = 0.f, a0 = 0.f;
        for (int j = 0; j < H2c; j++) { alpha += su[j] * szv[j]; beta += szv[j] * sBw[j]; }
        for (int j = 0; j < Hc;  j++) a0 += mu0[j] * (su[j] - su[Hc + j]);
        float c = beta;
        for (int k = KT - 2; k >= 0; k--) { g_coef[k] = c; c *= alpha; }
        g_coef[KT - 1] = 1.0f;                 // slot for q (selected in reduce)
        float bp = beta * a0;
        for (int e = 0; e < Tc - 1 && bp != 0.f; e++) bp *= alpha;
        g_bias = bp;
    }
}

// ---------------------------------------------------------------------------
// Reduce kernel: 2 rows per 256-thread block (128 threads per row).
// y[n] = bias + sum_k coef[k]*(w_k . x[n,T-KT+k,:]);  w_k = p except w_{KT-1}=q.
// Each thread: 8 independent float4 LDGs front-batched; no smem staging.
// ---------------------------------------------------------------------------
__global__ __launch_bounds__(256)
void urnn_reduce(const float* __restrict__ x, float* __restrict__ out)
{
    const int tid   = threadIdx.x;
    const int lane  = tid & 31;
    const int warp  = tid >> 5;           // 0..7
    const int half  = warp >> 2;          // 0 or 1: which row of the pair
    const int wh    = warp & 3;           // warp index within row (0..3)
    const int ht    = tid & 127;          // thread index within row (0..127)
    const int n     = blockIdx.x * 2 + half;

    const float4* xp = reinterpret_cast<const float4*>(
        x + (size_t)n * (Tc * Dc) + (size_t)(Tc - KT) * Dc);   // KT*Dc/4 = 1024 float4

    // Weight state (L2-broadcast hits after first wave)
    const float4 pv = __ldg(&reinterpret_cast<const float4*>(g_p)[lane]);
    const float4 qv = __ldg(&reinterpret_cast<const float4*>(g_q)[lane]);
    float cf[8];
    #pragma unroll
    for (int r = 0; r < 8; r++) cf[r] = __ldg(&g_coef[wh + r * 4]);   // warp-uniform

    // Stream x: 8 independent float4 loads per thread
    float4 xv[8];
    #pragma unroll
    for (int r = 0; r < 8; r++) xv[r] = xp[ht + r * 128];

    float acc = 0.f;
    #pragma unroll
    for (int r = 0; r < 8; r++) {
        const int k = wh + r * 4;                 // timestep index, warp-uniform
        const float4 wv = (k == KT - 1) ? qv : pv;
        const float d = xv[r].x * wv.x + xv[r].y * wv.y + xv[r].z * wv.z + xv[r].w * wv.w;
        acc += cf[r] * d;
    }

    #pragma unroll
    for (int off = 16; off; off >>= 1) acc += __shfl_down_sync(0xffffffffu, acc, off);
    __shared__ float wsum[8];
    if (lane == 0) wsum[warp] = acc;
    __syncthreads();
    // One thread per row finishes its half-block reduction
    if (tid < 2) {
        const float* ws = wsum + tid * 4;
        out[blockIdx.x * 2 + tid] = ws[0] + ws[1] + ws[2] + ws[3] + g_bias;
    }
}

extern "C" void kernel_launch(void* const* d_in, const int* in_sizes, int n_in,
                              void* d_out, int out_size)
{
    const float* inputs = (const float*)d_in[0];   // (1024, 512, 128)
    const float* C_w    = (const float*)d_in[1];   // (40, 128)
    const float* B_w    = (const float*)d_in[2];   // (1, 40)
    const float* refl   = (const float*)d_in[3];   // (2, 40)
    const float* theta  = (const float*)d_in[4];   // (3, 20)
    const float* mu0    = (const float*)d_in[5];   // (20,)
    float* out = (float*)d_out;                    // (1024,)

    setup_kernel<<<1, 256>>>(C_w, B_w, refl, theta, mu0);
    urnn_reduce<<<Nc / 2, 256>>>(inputs, out);
}

// round 6
// speedup vs baseline: 2.9108x; 1.3829x over previous
#include <cuda_runtime.h>
#include <math.h>

// Problem constants
constexpr int Hc   = 20;          // H
constexpr int H2c  = 40;          // 2H
constexpr int Tc   = 512;
constexpr int Dc   = 128;
constexpr int Nc   = 1024;
// Tail timesteps kept. |alpha| <= |u||z| = sqrt(2H)/H < 0.3163 rigorously,
// so truncation error <= alpha^{KT-1} ~ 3e-8 at KT=16 — far below fp32 noise.
constexpr int KT   = 16;
constexpr int ROWS_PER_BLK = 4;               // samples per block
constexpr int F4_PER_ROW   = KT * Dc / 4;     // 512 float4 per sample tail
constexpr float PIf = 3.14159265358979323846f;

// ---------------------------------------------------------------------------
// Single fused kernel (one graph node, one T_ovh).
//   recurrence(h) = (u . h) * z  (rank-1), so
//   y_n = q.x[n,T-1] + sum_{k<=KT-2} beta*alpha^{KT-2-k} (p.x[n,T-KT+k]) + bias
// Each block: issue 32KB of x via cp.async FIRST, compute the tiny closed-form
// setup while loads are in flight (grid=256 -> 1.7 blocks/SM, so the redundant
// setup costs ~1 us wall once, hidden under load latency), then dot + reduce.
// ---------------------------------------------------------------------------
__global__ __launch_bounds__(256)
void urnn_fused(const float* __restrict__ x,     // (1024,512,128)
                const float* __restrict__ Cw,    // (40,128)
                const float* __restrict__ Bw,    // (1,40)
                const float* __restrict__ refl,  // (2,40)
                const float* __restrict__ theta, // (3,20)
                const float* __restrict__ mu0,   // (20,)
                float* __restrict__ out)         // (1024,)
{
    __shared__ float4 sX[ROWS_PER_BLK * F4_PER_ROW];   // 32 KB
    __shared__ float tw_c[Hc], tw_s[Hc];
    __shared__ float e0c[Hc], e0s[Hc];
    __shared__ float z0r[Hc], z0i[Hc];
    __shared__ float e2c[Hc], e2s[Hc];
    __shared__ float r1[H2c], r2[H2c], sBw[H2c];
    __shared__ float su[H2c], szv[H2c];
    __shared__ float so_r[Hc], so_i[Hc];
    __shared__ float sp[Dc], sq[Dc], scoef[KT];
    __shared__ float vss1s, vss2s, t2x, t2y, sbias;
    __shared__ float wsum[8];

    const int tid = threadIdx.x;

    // ---- Issue x-tail loads FIRST (async, no registers held) ----
    // Block covers samples n0..n0+3; each sample's tail is 512 contiguous float4.
    {
        const int n0 = blockIdx.x * ROWS_PER_BLK;
        #pragma unroll
        for (int r = 0; r < 8; r++) {
            const int idx = tid + r * 256;                // 0..2047
            const int s   = idx >> 9;                     // sample within block
            const int w   = idx & (F4_PER_ROW - 1);       // float4 within sample
            const float4* src = reinterpret_cast<const float4*>(
                x + (size_t)(n0 + s) * (Tc * Dc) + (size_t)(Tc - KT) * Dc) + w;
            unsigned sa = (unsigned)__cvta_generic_to_shared(&sX[idx]);
            asm volatile("cp.async.cg.shared.global [%0], [%1], 16;\n"
                         :: "r"(sa), "l"(src));
        }
        asm volatile("cp.async.commit_group;\n");
    }

    // ---- Pre-stage: trig tables + operand staging ----
    if (tid < Hc) {
        float s, c;
        sincosf(2.0f * PIf * (float)tid / (float)Hc, &s, &c);
        tw_c[tid] = c; tw_s[tid] = s;
        sincosf(theta[tid], &s, &c);          e0c[tid] = c; e0s[tid] = s;
        sincosf(theta[Hc + tid], &s, &c);     z0r[tid] = c - s; z0i[tid] = c + s;
        sincosf(theta[2 * Hc + tid], &s, &c); e2c[tid] = c; e2s[tid] = s;
    }
    if (tid >= 32 && tid < 32 + H2c) {
        const int j = tid - 32;
        r1[j] = refl[j]; r2[j] = refl[H2c + j]; sBw[j] = Bw[j];
    }
    if (tid == 96)  { float v = 0.f; for (int k = 0; k < H2c; k++) { float r = refl[k];       v += r * r; } vss1s = v; }
    if (tid == 128) { float v = 0.f; for (int k = 0; k < H2c; k++) { float r = refl[H2c + k]; v += r * r; } vss2s = v; }
    __syncthreads();

    // ---- Stage A (warps 0-1): u_j = Im[(w_j/sqrtH)(1 - s1 V_m conj(v1_0))] ----
    if (tid < H2c) {
        const int j = tid;
        const int m = (j < Hc) ? j : j - Hc;
        float2 w;
        if (j < Hc) w = make_float2(e0c[m], e0s[m]);
        else        w = make_float2(-e0s[m], e0c[m]);     // i * e^{i th}
        const float sc1 = 2.0f / vss1s;
        float Vx = 0.f, Vy = 0.f;
        #pragma unroll 4
        for (int k = 0; k < Hc; k++) {
            const int mm = (m * k) % Hc;
            const float ck = tw_c[mm], sk = -tw_s[mm];    // exp(-2*pi*i*mm/H)
            const float vr = r1[k], vi = r1[Hc + k];
            Vx += vr * ck - vi * sk;
            Vy += vr * sk + vi * ck;
        }
        const float v0x = r1[0], v0y = -r1[Hc];           // conj(v1_0)
        const float gx = 1.0f - sc1 * (Vx * v0x - Vy * v0y);
        const float gy =        -sc1 * (Vx * v0y + Vy * v0x);
        su[j] = (w.x * gy + w.y * gx) * (1.0f / sqrtf((float)Hc));
    }
    // ---- Stage B1 (warp 2, concurrent): o = IFFT(z0)/sqrtH ----
    if (tid >= 64 && tid < 64 + Hc) {
        const int k = tid - 64;
        float ar = 0.f, ai = 0.f;
        #pragma unroll 4
        for (int m = 0; m < Hc; m++) {
            const int mm = (m * k) % Hc;
            const float ck = tw_c[mm], sk = tw_s[mm];     // exp(+2*pi*i*mm/H)
            ar += z0r[m] * ck - z0i[m] * sk;
            ai += z0r[m] * sk + z0i[m] * ck;
        }
        const float scale = 1.0f / ((float)Hc * sqrtf((float)Hc));
        so_r[k] = ar * scale; so_i[k] = ai * scale;
    }
    __syncthreads();

    // ---- Stage B2: t2 = s2*(v2^T o);  Stage D (warps 4-7): p = Cw^T u, q = Cw^T b ----
    if (tid == 0) {
        float tx = 0.f, ty = 0.f;
        for (int k = 0; k < Hc; k++) {
            const float vr = r2[k], vi = r2[Hc + k];
            tx += vr * so_r[k] - vi * so_i[k];
            ty += vr * so_i[k] + vi * so_r[k];
        }
        const float s2 = 2.0f / vss2s;
        t2x = tx * s2; t2y = ty * s2;
    }
    if (tid >= 128) {
        const int d = tid - 128;
        float p = 0.f, q = 0.f;
        #pragma unroll 8
        for (int j = 0; j < H2c; j++) {
            const float cw = __ldg(&Cw[j * Dc + d]);
            p += su[j] * cw;
            q += sBw[j] * cw;
        }
        sp[d] = p; sq[d] = q;
    }
    __syncthreads();

    // ---- Stage B3: apply reflection-2 + D3(theta2) -> z ----
    if (tid < Hc) {
        const int k = tid;
        const float vr = r2[k], vi = r2[Hc + k];
        const float ox = so_r[k] - (t2x * vr + t2y * vi);
        const float oy = so_i[k] - (t2y * vr - t2x * vi);
        const float c = e2c[k], s = e2s[k];
        szv[k]      = ox * c - oy * s;
        szv[Hc + k] = ox * s + oy * c;
    }
    __syncthreads();

    // ---- Stage C: alpha, beta, a0, coefficient ladder, bias ----
    if (tid == 0) {
        float alpha = 0.f, beta = 0.f, a0 = 0.f;
        for (int j = 0; j < H2c; j++) { alpha += su[j] * szv[j]; beta += szv[j] * sBw[j]; }
        for (int j = 0; j < Hc;  j++) a0 += mu0[j] * (su[j] - su[Hc + j]);
        float c = beta;
        for (int k = KT - 2; k >= 0; k--) { scoef[k] = c; c *= alpha; }
        scoef[KT - 1] = 1.0f;                               // slot for q
        float bp = beta * a0;
        for (int e = 0; e < Tc - 1 && bp != 0.f; e++) bp *= alpha;
        sbias = bp;
    }

    // ---- Wait for x tail, then dot ----
    asm volatile("cp.async.wait_group 0;\n" ::: "memory");
    __syncthreads();

    // 64 threads per sample; thread covers float4 indices st + 64r (r=0..7).
    // k = (st + 64r) >> 5 = 2r + warpInSample  -> warp-uniform.
    const int lane = tid & 31;
    const int warp = tid >> 5;                 // 0..7
    const int s    = tid >> 6;                 // sample within block (0..3)
    const int st   = tid & 63;                 // thread within sample
    const int wis  = (tid >> 5) & 1;           // warp within sample

    const float4 pv = reinterpret_cast<const float4*>(sp)[lane];
    const float4 qv = reinterpret_cast<const float4*>(sq)[lane];

    float acc = 0.f;
    #pragma unroll
    for (int r = 0; r < 8; r++) {
        const int k = 2 * r + wis;             // timestep, warp-uniform
        const float4 xv = sX[s * F4_PER_ROW + st + r * 64];
        const float4 wv = (k == KT - 1) ? qv : pv;
        const float d = xv.x * wv.x + xv.y * wv.y + xv.z * wv.z + xv.w * wv.w;
        acc += scoef[k] * d;
    }

    #pragma unroll
    for (int off = 16; off; off >>= 1) acc += __shfl_down_sync(0xffffffffu, acc, off);
    if (lane == 0) wsum[warp] = acc;
    __syncthreads();
    if (tid < ROWS_PER_BLK)
        out[blockIdx.x * ROWS_PER_BLK + tid] = wsum[2 * tid] + wsum[2 * tid + 1] + sbias;
}

extern "C" void kernel_launch(void* const* d_in, const int* in_sizes, int n_in,
                              void* d_out, int out_size)
{
    const float* inputs = (const float*)d_in[0];   // (1024, 512, 128)
    const float* C_w    = (const float*)d_in[1];   // (40, 128)
    const float* B_w    = (const float*)d_in[2];   // (1, 40)
    const float* refl   = (const float*)d_in[3];   // (2, 40)
    const float* theta  = (const float*)d_in[4];   // (3, 20)
    const float* mu0    = (const float*)d_in[5];   // (20,)
    float* out = (float*)d_out;                    // (1024,)

    urnn_fused<<<Nc / ROWS_PER_BLK, 256>>>(inputs, C_w, B_w, refl, theta, mu0, out);
}